// round 13
// baseline (speedup 1.0000x reference)
#include <cuda_runtime.h>
#include <cuda_bf16.h>
#include <cstdint>

#define D_MODEL   2048
#define HIDDEN    2048
#define NUM_HEADS 16
#define HEAD_DIM  128
#define BATCH     4
#define SEQ       2048
#define MROWS     (BATCH*SEQ)      // 8192
#define GK        2048
#define GN        2048
#define KA        4096             // split storage: [hi(2048) | lo(2048)]
#define NT3       96               // 3-term K': 3 * 2048 / 64

// tcgen05 is an arch-specific ('a') feature: only emit it in passes that have it.
#if defined(__CUDA_ARCH_FEAT_SM103_ALL) || defined(__CUDA_ARCH_FEAT_SM100_ALL) || \
    (defined(__CUDA_ARCH_SPECIFIC__) && (__CUDA_ARCH_SPECIFIC__ == 1030))
#define HAS_TCGEN05 1
#else
#define HAS_TCGEN05 0
#endif

// ---------------- scratch (device globals; no allocation allowed) ----------
__device__ float g_q[(size_t)MROWS * HIDDEN];        // [B,H,S,hd]
__device__ float g_k[(size_t)MROWS * HIDDEN];        // [B,H,S,hd]
__device__ float g_v[(size_t)MROWS * HIDDEN];        // [B,H,S,hd]
__device__ float g_ao[(size_t)MROWS * HIDDEN];       // [B,S,H*hd]
__device__ __nv_bfloat16 g_xs [(size_t)MROWS * KA];  // split(x): hi block | lo block
__device__ __nv_bfloat16 g_aos[(size_t)MROWS * KA];  // split(g_ao)
__device__ __nv_bfloat16 g_ws [4][(size_t)GN * KA];  // split(W^T): hi block | lo block

extern __shared__ char dyn_smem[];

// ---------------- PTX helpers ----------------------------------------------
__device__ __forceinline__ uint32_t smem_u32(const void* p) {
    uint32_t a;
    asm("{ .reg .u64 t; cvta.to.shared.u64 t, %1; cvt.u32.u64 %0, t; }"
        : "=r"(a) : "l"(p));
    return a;
}
__device__ __forceinline__ uint32_t elect1() {
    uint32_t p;
    asm volatile("{\n\t.reg .pred p;\n\telect.sync _|p, 0xFFFFFFFF;\n\t"
                 "selp.b32 %0, 1, 0, p;\n\t}" : "=r"(p));
    return p;
}
#define MBARRIER_INIT(addr, cnt) \
    asm volatile("mbarrier.init.shared.b64 [%0], %1;" :: "r"((uint32_t)(addr)), "r"((uint32_t)(cnt)) : "memory")
__device__ __forceinline__ void mbar_wait(uint32_t addr, int parity) {
    asm volatile(
        "{\n\t.reg .pred P;\n\t"
        "W_%=:\n\t"
        "mbarrier.try_wait.parity.acquire.cta.shared::cta.b64 P, [%0], %1, 0x989680;\n\t"
        "@P bra D_%=;\n\t"
        "bra W_%=;\n\t"
        "D_%=:\n\t}"
        :: "r"(addr), "r"(parity) : "memory");
}
#define FENCE_PROXY_ASYNC() asm volatile("fence.proxy.async.shared::cta;" ::: "memory")
#define SW128(off) ((off) ^ (((off) >> 3) & 0x70))

#if HAS_TCGEN05
#define TCGEN05_ALLOC(sa, n) \
    asm volatile("tcgen05.alloc.cta_group::1.sync.aligned.shared::cta.b32 [%0], %1;" \
                 :: "r"((uint32_t)(sa)), "r"((uint32_t)(n)) : "memory")
#define TCGEN05_DEALLOC(t, n) \
    asm volatile("tcgen05.dealloc.cta_group::1.sync.aligned.b32 %0, %1;" :: "r"(t), "r"((uint32_t)(n)))
#define TCGEN05_RELINQ() \
    asm volatile("tcgen05.relinquish_alloc_permit.cta_group::1.sync.aligned;")
#define TCGEN05_COMMIT(mb) \
    asm volatile("tcgen05.commit.cta_group::1.mbarrier::arrive::one.shared::cluster.b64 [%0];" \
                 :: "r"((uint32_t)(mb)) : "memory")
#define TCGEN05_FENCE_AFTER() asm volatile("tcgen05.fence::after_thread_sync;" ::: "memory")
#define TCGEN05_WAIT_LD()     asm volatile("tcgen05.wait::ld.sync.aligned;" ::: "memory")
#define TCGEN05_LD_X32(r, ta) \
    asm volatile( \
        "tcgen05.ld.sync.aligned.32x32b.x32.b32 " \
        "{%0, %1, %2, %3, %4, %5, %6, %7, " \
        " %8, %9, %10, %11, %12, %13, %14, %15, " \
        " %16, %17, %18, %19, %20, %21, %22, %23, " \
        " %24, %25, %26, %27, %28, %29, %30, %31}, [%32];" \
        : "=r"((r)[0]),  "=r"((r)[1]),  "=r"((r)[2]),  "=r"((r)[3]), \
          "=r"((r)[4]),  "=r"((r)[5]),  "=r"((r)[6]),  "=r"((r)[7]), \
          "=r"((r)[8]),  "=r"((r)[9]),  "=r"((r)[10]), "=r"((r)[11]), \
          "=r"((r)[12]), "=r"((r)[13]), "=r"((r)[14]), "=r"((r)[15]), \
          "=r"((r)[16]), "=r"((r)[17]), "=r"((r)[18]), "=r"((r)[19]), \
          "=r"((r)[20]), "=r"((r)[21]), "=r"((r)[22]), "=r"((r)[23]), \
          "=r"((r)[24]), "=r"((r)[25]), "=r"((r)[26]), "=r"((r)[27]), \
          "=r"((r)[28]), "=r"((r)[29]), "=r"((r)[30]), "=r"((r)[31]) \
        : "r"(ta))

static constexpr uint64_t SMEM_DESC_BASE_SW128 =
    (uint64_t(2) << 61) | (uint64_t(1) << 46) | (uint64_t(64) << 32) | (uint64_t(1) << 16);
#define MAKE_SMEM_DESC(ba) (SMEM_DESC_BASE_SW128 | ((uint64_t)((ba) >> 4) & 0x3FFF))

__device__ __forceinline__ void mma_f16_ss_cg1(uint32_t d, uint64_t ad, uint64_t bd,
                                               uint32_t idesc, uint32_t en) {
    asm volatile(
        "{\n\t.reg .pred p;\n\tsetp.ne.u32 p, %5, 0;\n\t"
        "tcgen05.mma.cta_group::1.kind::f16 [%0], %1, %2, %3, {%4, %4, %4, %4}, p;\n\t}"
        :: "r"(d), "l"(ad), "l"(bd), "r"(idesc), "r"(0u), "r"(en) : "memory");
}
#endif  // HAS_TCGEN05

// ---------------- split-bf16 helpers ----------------------------------------
__device__ __forceinline__ void split2(float x, unsigned short& h, unsigned short& l) {
    __nv_bfloat16 hb = __float2bfloat16(x);
    __nv_bfloat16 lb = __float2bfloat16(x - __bfloat162float(hb));
    h = __bfloat16_as_ushort(hb);
    l = __bfloat16_as_ushort(lb);
}

// ---- conv: [M,2048] fp32 -> [M,4096] bf16  (hi block | lo block) -----------
template<int SRC>  // 0: param x -> g_xs     1: g_ao -> g_aos
__global__ __launch_bounds__(256) void conv_split(const float* __restrict__ xin)
{
    const float* src = (SRC == 0) ? xin : g_ao;
    __nv_bfloat16* dst = (SRC == 0) ? g_xs : g_aos;
    const int NG = MROWS * GK / 8;            // 8-element groups
    for (int g = blockIdx.x * blockDim.x + threadIdx.x; g < NG; g += gridDim.x * blockDim.x) {
        const int m  = g >> 8;                // 256 groups per row
        const int kb = (g & 255) << 3;
        const float4 v0 = *(const float4*)&src[(size_t)m * GK + kb];
        const float4 v1 = *(const float4*)&src[(size_t)m * GK + kb + 4];
        unsigned short h[8], l[8];
        split2(v0.x, h[0], l[0]); split2(v0.y, h[1], l[1]);
        split2(v0.z, h[2], l[2]); split2(v0.w, h[3], l[3]);
        split2(v1.x, h[4], l[4]); split2(v1.y, h[5], l[5]);
        split2(v1.z, h[6], l[6]); split2(v1.w, h[7], l[7]);
        uint4 ho, lo;
        ho.x = (uint32_t)h[0] | ((uint32_t)h[1] << 16);
        ho.y = (uint32_t)h[2] | ((uint32_t)h[3] << 16);
        ho.z = (uint32_t)h[4] | ((uint32_t)h[5] << 16);
        ho.w = (uint32_t)h[6] | ((uint32_t)h[7] << 16);
        lo.x = (uint32_t)l[0] | ((uint32_t)l[1] << 16);
        lo.y = (uint32_t)l[2] | ((uint32_t)l[3] << 16);
        lo.z = (uint32_t)l[4] | ((uint32_t)l[5] << 16);
        lo.w = (uint32_t)l[6] | ((uint32_t)l[7] << 16);
        *(uint4*)&dst[(size_t)m * KA + kb]        = ho;
        *(uint4*)&dst[(size_t)m * KA + 2048 + kb] = lo;
    }
}

// ---- conv: W [K,N] fp32 -> Wt [N,4096] bf16 (transpose + split blocks) -----
template<int IDX>
__global__ __launch_bounds__(256) void conv_wT(const float* __restrict__ W)
{
    __shared__ float smt[32][33];
    const int k0 = blockIdx.y * 32, n0 = blockIdx.x * 32;
    const int tx = threadIdx.x, ty = threadIdx.y;  // 32x8
#pragma unroll
    for (int r = 0; r < 4; r++)
        smt[ty + 8 * r][tx] = W[(size_t)(k0 + ty + 8 * r) * GN + n0 + tx];
    __syncthreads();
#pragma unroll
    for (int r = 0; r < 4; r++) {
        const int n = n0 + ty + 8 * r;
        const int k = k0 + tx;
        unsigned short h, l;
        split2(smt[tx][ty + 8 * r], h, l);
        *(unsigned short*)&g_ws[IDX][(size_t)n * KA + k]        = h;
        *(unsigned short*)&g_ws[IDX][(size_t)n * KA + 2048 + k] = l;
    }
}

// ---------------- GEMM: D[128,256] per CTA, 3-term split, 3-stage -----------
// K' = 6144 as 96 tiles of 64 bf16:
//   kt in [0,32):  A hi, B hi     (hi*hi)
//   kt in [32,64): A lo, B hi     (lo*hi)
//   kt in [64,96): A hi, B lo     (hi*lo)      [lo*lo ~ eps^2 dropped]
// MODE 0: Q -> RoPE -> g_q   MODE 1: K -> RoPE -> g_k
// MODE 2: V -> g_v           MODE 3: O-proj -> param out
#define TBK     64
#define TN      256
#define SM_TMEM 0
#define SM_MB(s) (8 + 8 * (s))
#define STG_SZ   49152                      // A 16KB + B 32KB
#define SM_A(s)  (1024 + (s) * STG_SZ)
#define SM_B(s)  (SM_A(s) + 16384)
#define TG_SMEM  (1024 + 3 * STG_SZ)        // 148480 B

template<int MODE>
__global__ __launch_bounds__(256) void tgemm(
    const float* __restrict__ Afp, const float* __restrict__ Wfp,
    const float* __restrict__ bias, float* __restrict__ outp,
    const float* __restrict__ cosT, const float* __restrict__ sinT)
{
#if HAS_TCGEN05
    // ======================= tcgen05 path =======================
    const uint32_t sb = smem_u32(dyn_smem);
    const int tid = threadIdx.x;
    const int wid = tid >> 5, lid = tid & 31;
    const int m0 = blockIdx.y * 128, n0 = blockIdx.x * TN;

    const __nv_bfloat16* Ain = (MODE == 3) ? g_aos : g_xs;
    const __nv_bfloat16* Bin = g_ws[MODE];

    if (wid == 0) TCGEN05_ALLOC(sb + SM_TMEM, 256);
    if (tid == 0) {
        MBARRIER_INIT(SM_MB(0) + sb, 1);
        MBARRIER_INIT(SM_MB(1) + sb, 1);
        MBARRIER_INIT(SM_MB(2) + sb, 1);
    }
    __syncthreads();
    uint32_t tmem;
    asm volatile("ld.shared.b32 %0, [%1];" : "=r"(tmem) : "r"(sb + SM_TMEM));

    // loader mapping: A = 1024 16B-chunks (4/thread), B = 2048 (8/thread)
    const int arow = tid >> 1, ac16 = (tid & 1) << 2;    // A: rows 0..127, chunks {0..3}/{4..7}
    const int brow = tid >> 3 << 0, bc16 = tid & 7;      // B base row 0..31, chunk 0..7
    uint4 va[4], vb[8];

    auto ldg = [&](int kt) {
        const int acol = (kt < 32) ? kt * TBK : (kt < 64) ? 2048 + (kt - 32) * TBK
                                              : (kt - 64) * TBK;
        const int bcol = (kt < 32) ? kt * TBK : (kt < 64) ? (kt - 32) * TBK
                                              : 2048 + (kt - 64) * TBK;
#pragma unroll
        for (int i = 0; i < 4; i++)
            va[i] = *(const uint4*)&Ain[(size_t)(m0 + arow) * KA + acol + (ac16 + i) * 8];
#pragma unroll
        for (int i = 0; i < 8; i++)
            vb[i] = *(const uint4*)&Bin[(size_t)(n0 + (tid >> 3) + i * 32) * KA + bcol + bc16 * 8];
    };
    auto sts = [&](int st) {
#pragma unroll
        for (int i = 0; i < 4; i++) {
            const uint32_t so = SW128((uint32_t)(arow * 128 + (ac16 + i) * 16));
            *(uint4*)(dyn_smem + SM_A(st) + so) = va[i];
        }
#pragma unroll
        for (int i = 0; i < 8; i++) {
            const int r = (tid >> 3) + i * 32;
            const uint32_t so = SW128((uint32_t)(r * 128 + bc16 * 16));
            *(uint4*)(dyn_smem + SM_B(st) + so) = vb[i];
        }
    };

    // prologue: tiles 0,1 into stages 0,1
    ldg(0); sts(0);
    ldg(1); sts(1);
    FENCE_PROXY_ASYNC();
    __syncthreads();

    const uint32_t idesc = (1u << 4) | (1u << 7) | (1u << 10) | ((TN / 8) << 17) | (8u << 24);
    int ph[3] = {0, 0, 0};

    for (int kt = 0; kt < NT3; kt++) {
        const int cur = kt % 3;
        if (kt + 2 < NT3) ldg(kt + 2);          // prefetch into regs
        if (wid == 0 && elect1()) {
            const uint64_t ad = MAKE_SMEM_DESC(sb + SM_A(cur));
            const uint64_t bd = MAKE_SMEM_DESC(sb + SM_B(cur));
#pragma unroll
            for (int s = 0; s < 4; s++)          // 4 x K=16 steps cover TBK=64
                mma_f16_ss_cg1(tmem, ad + s * 2, bd + s * 2, idesc,
                               (kt > 0 || s > 0) ? 1u : 0u);
            TCGEN05_COMMIT(sb + SM_MB(cur));
        }
        if (kt + 2 < NT3) {
            const int nx = (kt + 2) % 3;
            if (kt + 2 >= 3) { mbar_wait(sb + SM_MB(nx), ph[nx]); ph[nx] ^= 1; }
            sts(nx);
            FENCE_PROXY_ASYNC();
        }
        __syncthreads();
    }

    // final MMA group: stage (NT3-1)%3 == 2 (in-order pipe => all done)
    mbar_wait(sb + SM_MB(2), ph[2]);
    TCGEN05_FENCE_AFTER();

    if (wid < 4) {
        const int m = m0 + wid * 32 + lid;
        const int bb = m >> 11, s = m & 2047;
#pragma unroll
        for (int nb = 0; nb < 8; nb++) {
            uint32_t r[32];
            TCGEN05_LD_X32(r, tmem + nb * 32);
            TCGEN05_WAIT_LD();
            const int nbase = n0 + nb * 32;
            const int hh = nbase >> 7;
            const int d0 = nbase & 127;
            float w[32];
            if (MODE <= 1) {
#pragma unroll
                for (int c = 0; c < 32; c += 2) {
                    const int n = nbase + c;
                    const float v0 = __uint_as_float(r[c])     + bias[n];
                    const float v1 = __uint_as_float(r[c + 1]) + bias[n + 1];
                    const int i0 = (n & 127) >> 1;
                    const float cv = cosT[s * (HEAD_DIM / 2) + i0];
                    const float sv = sinT[s * (HEAD_DIM / 2) + i0];
                    w[c]     = v0 * cv - v1 * sv;
                    w[c + 1] = v0 * sv + v1 * cv;
                }
            } else {
#pragma unroll
                for (int c = 0; c < 32; c++)
                    w[c] = __uint_as_float(r[c]) + bias[nbase + c];
            }
            if (MODE == 3) {
#pragma unroll
                for (int c = 0; c < 32; c += 4)
                    *(float4*)&outp[(size_t)m * GN + nbase + c] =
                        make_float4(w[c], w[c + 1], w[c + 2], w[c + 3]);
            } else {
                float* dst = (MODE == 0) ? g_q : (MODE == 1) ? g_k : g_v;
                const size_t off =
                    ((size_t)(bb * NUM_HEADS + hh) * SEQ + s) * HEAD_DIM + d0;
#pragma unroll
                for (int c = 0; c < 32; c += 4)
                    *(float4*)&dst[off + c] =
                        make_float4(w[c], w[c + 1], w[c + 2], w[c + 3]);
            }
        }
    }
    __syncthreads();
    if (wid == 0) { TCGEN05_RELINQ(); TCGEN05_DEALLOC(tmem, 256); }

#else
    // ============ fallback: proven fp32 scalar GEMM (two 128-wide halves) ============
    float* As = (float*)dyn_smem;                     // [2][16][132]
    float* Bs = (float*)dyn_smem + 2 * 16 * 132;      // [2][16][128]
#define AS_(b,k,r) As[((b) * 16 + (k)) * 132 + (r)]
#define BS_(b,k,c) Bs[((b) * 16 + (k)) * 128 + (c)]

    const int tid = threadIdx.x;
    const int m0 = blockIdx.y * 128;
    const float* Ap = (MODE == 3) ? g_ao : Afp;
    const float* W  = Wfp;

    const int r0 = (tid >> 4) << 3;
    const int c0 = (tid & 15) << 3;

    int a_row[2], a_k[2], b_row[2], b_col[2];
#pragma unroll
    for (int j = 0; j < 2; j++) {
        int lin = tid + j * 256;
        a_row[j] = lin >> 2;  a_k[j] = (lin & 3) << 2;
        b_row[j] = lin >> 5;  b_col[j] = (lin & 31) << 2;
    }

    for (int nh = 0; nh < 2; nh++) {
        const int n0 = blockIdx.x * TN + nh * 128;
        __syncthreads();

        float acc[8][8];
#pragma unroll
        for (int i = 0; i < 8; i++)
#pragma unroll
            for (int j = 0; j < 8; j++) acc[i][j] = 0.f;

        float4 pa[2], pb[2];
#pragma unroll
        for (int j = 0; j < 2; j++) {
            pa[j] = *(const float4*)&Ap[(size_t)(m0 + a_row[j]) * GK + a_k[j]];
            pb[j] = *(const float4*)&W[(size_t)b_row[j] * GN + n0 + b_col[j]];
        }
#pragma unroll
        for (int j = 0; j < 2; j++) {
            AS_(0, a_k[j] + 0, a_row[j]) = pa[j].x;
            AS_(0, a_k[j] + 1, a_row[j]) = pa[j].y;
            AS_(0, a_k[j] + 2, a_row[j]) = pa[j].z;
            AS_(0, a_k[j] + 3, a_row[j]) = pa[j].w;
            *(float4*)&BS_(0, b_row[j], b_col[j]) = pb[j];
        }
        __syncthreads();

        const int NT = GK / 16;
        for (int kt = 0; kt < NT; kt++) {
            const int cur = kt & 1;
            if (kt + 1 < NT) {
#pragma unroll
                for (int j = 0; j < 2; j++) {
                    pa[j] = *(const float4*)&Ap[(size_t)(m0 + a_row[j]) * GK + (kt + 1) * 16 + a_k[j]];
                    pb[j] = *(const float4*)&W[(size_t)((kt + 1) * 16 + b_row[j]) * GN + n0 + b_col[j]];
                }
            }
#pragma unroll
            for (int kk = 0; kk < 16; kk++) {
                float a[8], b[8];
                *(float4*)&a[0] = *(const float4*)&AS_(cur, kk, r0);
                *(float4*)&a[4] = *(const float4*)&AS_(cur, kk, r0 + 4);
                *(float4*)&b[0] = *(const float4*)&BS_(cur, kk, c0);
                *(float4*)&b[4] = *(const float4*)&BS_(cur, kk, c0 + 4);
#pragma unroll
                for (int i = 0; i < 8; i++)
#pragma unroll
                    for (int j = 0; j < 8; j++)
                        acc[i][j] += a[i] * b[j];
            }
            if (kt + 1 < NT) {
                const int nxt = cur ^ 1;
#pragma unroll
                for (int j = 0; j < 2; j++) {
                    AS_(nxt, a_k[j] + 0, a_row[j]) = pa[j].x;
                    AS_(nxt, a_k[j] + 1, a_row[j]) = pa[j].y;
                    AS_(nxt, a_k[j] + 2, a_row[j]) = pa[j].z;
                    AS_(nxt, a_k[j] + 3, a_row[j]) = pa[j].w;
                    *(float4*)&BS_(nxt, b_row[j], b_col[j]) = pb[j];
                }
            }
            __syncthreads();
        }

        float bv[8];
        *(float4*)&bv[0] = *(const float4*)&bias[n0 + c0];
        *(float4*)&bv[4] = *(const float4*)&bias[n0 + c0 + 4];

#pragma unroll
        for (int i = 0; i < 8; i++) {
            const int m = m0 + r0 + i;
            float v[8];
#pragma unroll
            for (int j = 0; j < 8; j++) v[j] = acc[i][j] + bv[j];

            if (MODE == 3) {
                *(float4*)&outp[(size_t)m * GN + n0 + c0]     = make_float4(v[0], v[1], v[2], v[3]);
                *(float4*)&outp[(size_t)m * GN + n0 + c0 + 4] = make_float4(v[4], v[5], v[6], v[7]);
            } else {
                const int bb = m >> 11;
                const int s  = m & 2047;
                const int hh = (n0 + c0) >> 7;
                const int d0 = (n0 + c0) & 127;
                float w[8];
                if (MODE <= 1) {
                    const int i0 = d0 >> 1;
#pragma unroll
                    for (int p = 0; p < 4; p++) {
                        float cv = cosT[s * (HEAD_DIM / 2) + i0 + p];
                        float sv = sinT[s * (HEAD_DIM / 2) + i0 + p];
                        w[2 * p]     = v[2 * p] * cv - v[2 * p + 1] * sv;
                        w[2 * p + 1] = v[2 * p] * sv + v[2 * p + 1] * cv;
                    }
                } else {
#pragma unroll
                    for (int j = 0; j < 8; j++) w[j] = v[j];
                }
                float* dst = (MODE == 0) ? g_q : (MODE == 1) ? g_k : g_v;
                size_t o = ((size_t)(bb * NUM_HEADS + hh) * SEQ + s) * HEAD_DIM + d0;
                *(float4*)&dst[o]     = make_float4(w[0], w[1], w[2], w[3]);
                *(float4*)&dst[o + 4] = make_float4(w[4], w[5], w[6], w[7]);
            }
        }
    }
#undef AS_
#undef BS_
#endif  // HAS_TCGEN05
}

// ---------------- flash attention (causal), fp32 — proven R4 version -------
#define ATTN_SMEM_FLOATS 29376
#define ATTN_SMEM_BYTES  (ATTN_SMEM_FLOATS * 4)

__global__ __launch_bounds__(256, 1) void attn_kernel()
{
    float* sm = (float*)dyn_smem;
    float* Qs   = sm;
    float* Ks   = sm + 8192;
    float* Vs   = sm + 16640;
    float* Ss   = sm + 24832;
    float* rowm = sm + 29184;
    float* rowl = sm + 29248;
    float* rowa = sm + 29312;

    const int tid = threadIdx.x;
    const int qt = blockIdx.x, h = blockIdx.y, b = blockIdx.z;
    const int q0 = qt * 64;
    const size_t base = ((size_t)(b * NUM_HEADS + h)) * SEQ * HEAD_DIM;
    const float scale = 0.088388347648318447f;  // 1/sqrt(128)

    for (int idx = tid; idx < 2048; idx += 256) {
        int r = idx >> 5, c4 = (idx & 31) << 2;
        float4 v = *(const float4*)&g_q[base + (size_t)(q0 + r) * HEAD_DIM + c4];
        v.x *= scale; v.y *= scale; v.z *= scale; v.w *= scale;
        *(float4*)&Qs[r * 128 + c4] = v;
    }
    if (tid < 64) { rowm[tid] = -1e30f; rowl[tid] = 0.f; }

    const int org = tid >> 5;
    const int ocg = tid & 31;
    const int srg = tid >> 4;
    const int scg = tid & 15;

    float oacc[8][4];
#pragma unroll
    for (int i = 0; i < 8; i++)
#pragma unroll
        for (int u = 0; u < 4; u++) oacc[i][u] = 0.f;

    for (int t = 0; t <= qt; t++) {
        const int kv0 = t * 64;
        __syncthreads();
        for (int idx = tid; idx < 2048; idx += 256) {
            int r = idx >> 5, c4 = (idx & 31) << 2;
            *(float4*)&Ks[r * 132 + c4] =
                *(const float4*)&g_k[base + (size_t)(kv0 + r) * HEAD_DIM + c4];
            *(float4*)&Vs[r * 128 + c4] =
                *(const float4*)&g_v[base + (size_t)(kv0 + r) * HEAD_DIM + c4];
        }
        __syncthreads();

        float sacc[4][4];
#pragma unroll
        for (int i = 0; i < 4; i++)
#pragma unroll
            for (int j = 0; j < 4; j++) sacc[i][j] = 0.f;

#pragma unroll 8
        for (int c = 0; c < 128; c += 4) {
            float4 q4[4], k4[4];
#pragma unroll
            for (int i = 0; i < 4; i++)
                q4[i] = *(const float4*)&Qs[(srg * 4 + i) * 128 + c];
#pragma unroll
            for (int j = 0; j < 4; j++)
                k4[j] = *(const float4*)&Ks[(scg + 16 * j) * 132 + c];
#pragma unroll
            for (int i = 0; i < 4; i++)
#pragma unroll
                for (int j = 0; j < 4; j++)
                    sacc[i][j] += q4[i].x * k4[j].x + q4[i].y * k4[j].y +
                                  q4[i].z * k4[j].z + q4[i].w * k4[j].w;
        }
#pragma unroll
        for (int i = 0; i < 4; i++) {
            const int qg = q0 + srg * 4 + i;
#pragma unroll
            for (int j = 0; j < 4; j++) {
                const int kg = kv0 + scg + 16 * j;
                Ss[(srg * 4 + i) * 68 + scg + 16 * j] =
                    (kg <= qg) ? sacc[i][j] : -1e30f;
            }
        }
        __syncthreads();

        {
            const int row = tid >> 2, seg = tid & 3;
            float* srow = &Ss[row * 68 + seg * 16];
            const float mold = rowm[row];
            float mx = -1e30f;
#pragma unroll
            for (int j = 0; j < 16; j++) mx = fmaxf(mx, srow[j]);
            mx = fmaxf(mx, __shfl_xor_sync(0xffffffffu, mx, 1));
            mx = fmaxf(mx, __shfl_xor_sync(0xffffffffu, mx, 2));
            mx = fmaxf(mx, mold);
            float l = 0.f;
#pragma unroll
            for (int j = 0; j < 16; j++) {
                float p = __expf(srow[j] - mx);
                srow[j] = p;
                l += p;
            }
            l += __shfl_xor_sync(0xffffffffu, l, 1);
            l += __shfl_xor_sync(0xffffffffu, l, 2);
            if (seg == 0) {
                float alpha = __expf(mold - mx);
                rowa[row] = alpha;
                rowl[row] = rowl[row] * alpha + l;
                rowm[row] = mx;
            }
        }
        __syncthreads();

#pragma unroll
        for (int i = 0; i < 8; i++) {
            float a = rowa[org * 8 + i];
#pragma unroll
            for (int u = 0; u < 4; u++) oacc[i][u] *= a;
        }
#pragma unroll 4
        for (int j = 0; j < 64; j += 4) {
            float4 v0 = *(const float4*)&Vs[(j + 0) * 128 + ocg * 4];
            float4 v1 = *(const float4*)&Vs[(j + 1) * 128 + ocg * 4];
            float4 v2 = *(const float4*)&Vs[(j + 2) * 128 + ocg * 4];
            float4 v3 = *(const float4*)&Vs[(j + 3) * 128 + ocg * 4];
#pragma unroll
            for (int i = 0; i < 8; i++) {
                float4 p = *(const float4*)&Ss[(org * 8 + i) * 68 + j];
                oacc[i][0] += p.x * v0.x + p.y * v1.x + p.z * v2.x + p.w * v3.x;
                oacc[i][1] += p.x * v0.y + p.y * v1.y + p.z * v2.y + p.w * v3.y;
                oacc[i][2] += p.x * v0.z + p.y * v1.z + p.z * v2.z + p.w * v3.z;
                oacc[i][3] += p.x * v0.w + p.y * v1.w + p.z * v2.w + p.w * v3.w;
            }
        }
    }

#pragma unroll
    for (int i = 0; i < 8; i++) {
        const int row = org * 8 + i;
        const float il = 1.0f / rowl[row];
        size_t o = ((size_t)(b * SEQ + q0 + row)) * HIDDEN + h * HEAD_DIM + ocg * 4;
        *(float4*)&g_ao[o] = make_float4(oacc[i][0] * il, oacc[i][1] * il,
                                         oacc[i][2] * il, oacc[i][3] * il);
    }
}

// ---------------- launch ---------------------------------------------------
extern "C" void kernel_launch(void* const* d_in, const int* in_sizes, int n_in,
                              void* d_out, int out_size)
{
    const float* x    = (const float*)d_in[0];
    const float* wq   = (const float*)d_in[1];
    const float* bq   = (const float*)d_in[2];
    const float* wk   = (const float*)d_in[3];
    const float* bk_  = (const float*)d_in[4];
    const float* wv   = (const float*)d_in[5];
    const float* bv   = (const float*)d_in[6];
    const float* wo   = (const float*)d_in[7];
    const float* bo   = (const float*)d_in[8];
    const float* cosT = (const float*)d_in[9];
    const float* sinT = (const float*)d_in[10];
    float* out = (float*)d_out;

    cudaFuncSetAttribute(tgemm<0>, cudaFuncAttributeMaxDynamicSharedMemorySize, TG_SMEM);
    cudaFuncSetAttribute(tgemm<1>, cudaFuncAttributeMaxDynamicSharedMemorySize, TG_SMEM);
    cudaFuncSetAttribute(tgemm<2>, cudaFuncAttributeMaxDynamicSharedMemorySize, TG_SMEM);
    cudaFuncSetAttribute(tgemm<3>, cudaFuncAttributeMaxDynamicSharedMemorySize, TG_SMEM);
    cudaFuncSetAttribute(attn_kernel, cudaFuncAttributeMaxDynamicSharedMemorySize, ATTN_SMEM_BYTES);

    // split conversions
    conv_split<0><<<4096, 256>>>(x);
    conv_wT<0><<<dim3(GN / 32, GK / 32), dim3(32, 8)>>>(wq);
    conv_wT<1><<<dim3(GN / 32, GK / 32), dim3(32, 8)>>>(wk);
    conv_wT<2><<<dim3(GN / 32, GK / 32), dim3(32, 8)>>>(wv);
    conv_wT<3><<<dim3(GN / 32, GK / 32), dim3(32, 8)>>>(wo);

    dim3 ggrid(GN / TN, MROWS / 128);  // (8, 64)
    tgemm<0><<<ggrid, 256, TG_SMEM>>>(x, wq, bq,  nullptr, cosT, sinT);
    tgemm<1><<<ggrid, 256, TG_SMEM>>>(x, wk, bk_, nullptr, cosT, sinT);
    tgemm<2><<<ggrid, 256, TG_SMEM>>>(x, wv, bv,  nullptr, nullptr, nullptr);

    attn_kernel<<<dim3(SEQ / 64, NUM_HEADS, BATCH), 256, ATTN_SMEM_BYTES>>>();

    conv_split<1><<<4096, 256>>>(nullptr);
    tgemm<3><<<ggrid, 256, TG_SMEM>>>(nullptr, wo, bo, out, nullptr, nullptr);
}

// round 17
// speedup vs baseline: 1.0103x; 1.0103x over previous
#include <cuda_runtime.h>
#include <cuda_bf16.h>
#include <cstdint>

#define D_MODEL   2048
#define HIDDEN    2048
#define NUM_HEADS 16
#define HEAD_DIM  128
#define BATCH     4
#define SEQ       2048
#define MROWS     (BATCH*SEQ)      // 8192
#define GK        2048
#define GN        2048
#define KA        4096             // split storage: [hi(2048) | lo(2048)]
#define NT3       96               // 3-term K': 3 * 2048 / 64

#if defined(__CUDA_ARCH_FEAT_SM103_ALL) || defined(__CUDA_ARCH_FEAT_SM100_ALL) || \
    (defined(__CUDA_ARCH_SPECIFIC__) && (__CUDA_ARCH_SPECIFIC__ == 1030))
#define HAS_TCGEN05 1
#else
#define HAS_TCGEN05 0
#endif

// ---------------- scratch (device globals; no allocation allowed) ----------
__device__ float g_q[(size_t)MROWS * HIDDEN];        // [B,H,S,hd]
__device__ float g_k[(size_t)MROWS * HIDDEN];        // [B,H,S,hd]
__device__ float g_v[(size_t)MROWS * HIDDEN];        // [B,H,S,hd]
__device__ float g_ao[(size_t)MROWS * HIDDEN];       // [B,S,H*hd]
__device__ __nv_bfloat16 g_xs [(size_t)MROWS * KA];  // split(x): hi | lo
__device__ __nv_bfloat16 g_aos[(size_t)MROWS * KA];  // split(g_ao)
__device__ __nv_bfloat16 g_ws [4][(size_t)GN * KA];  // split(W^T): hi | lo

extern __shared__ char dyn_smem[];

// ---------------- PTX helpers ----------------------------------------------
__device__ __forceinline__ uint32_t smem_u32(const void* p) {
    uint32_t a;
    asm("{ .reg .u64 t; cvta.to.shared.u64 t, %1; cvt.u32.u64 %0, t; }"
        : "=r"(a) : "l"(p));
    return a;
}
__device__ __forceinline__ uint32_t elect1() {
    uint32_t p;
    asm volatile("{\n\t.reg .pred p;\n\telect.sync _|p, 0xFFFFFFFF;\n\t"
                 "selp.b32 %0, 1, 0, p;\n\t}" : "=r"(p));
    return p;
}
#define MBARRIER_INIT(addr, cnt) \
    asm volatile("mbarrier.init.shared.b64 [%0], %1;" :: "r"((uint32_t)(addr)), "r"((uint32_t)(cnt)) : "memory")
__device__ __forceinline__ void mbar_wait(uint32_t addr, int parity) {
    asm volatile(
        "{\n\t.reg .pred P;\n\t"
        "W_%=:\n\t"
        "mbarrier.try_wait.parity.acquire.cta.shared::cta.b64 P, [%0], %1, 0x989680;\n\t"
        "@P bra D_%=;\n\t"
        "bra W_%=;\n\t"
        "D_%=:\n\t}"
        :: "r"(addr), "r"(parity) : "memory");
}
#define FENCE_PROXY_ASYNC() asm volatile("fence.proxy.async.shared::cta;" ::: "memory")
#define SW128(off) ((off) ^ (((off) >> 3) & 0x70))

#if HAS_TCGEN05
#define TCGEN05_ALLOC(sa, n) \
    asm volatile("tcgen05.alloc.cta_group::1.sync.aligned.shared::cta.b32 [%0], %1;" \
                 :: "r"((uint32_t)(sa)), "r"((uint32_t)(n)) : "memory")
#define TCGEN05_DEALLOC(t, n) \
    asm volatile("tcgen05.dealloc.cta_group::1.sync.aligned.b32 %0, %1;" :: "r"(t), "r"((uint32_t)(n)))
#define TCGEN05_RELINQ() \
    asm volatile("tcgen05.relinquish_alloc_permit.cta_group::1.sync.aligned;")
#define TCGEN05_COMMIT(mb) \
    asm volatile("tcgen05.commit.cta_group::1.mbarrier::arrive::one.shared::cluster.b64 [%0];" \
                 :: "r"((uint32_t)(mb)) : "memory")
#define TCGEN05_FENCE_AFTER() asm volatile("tcgen05.fence::after_thread_sync;" ::: "memory")
#define TCGEN05_WAIT_LD()     asm volatile("tcgen05.wait::ld.sync.aligned;" ::: "memory")
#define TCGEN05_LD_X32(r, ta) \
    asm volatile( \
        "tcgen05.ld.sync.aligned.32x32b.x32.b32 " \
        "{%0, %1, %2, %3, %4, %5, %6, %7, " \
        " %8, %9, %10, %11, %12, %13, %14, %15, " \
        " %16, %17, %18, %19, %20, %21, %22, %23, " \
        " %24, %25, %26, %27, %28, %29, %30, %31}, [%32];" \
        : "=r"((r)[0]),  "=r"((r)[1]),  "=r"((r)[2]),  "=r"((r)[3]), \
          "=r"((r)[4]),  "=r"((r)[5]),  "=r"((r)[6]),  "=r"((r)[7]), \
          "=r"((r)[8]),  "=r"((r)[9]),  "=r"((r)[10]), "=r"((r)[11]), \
          "=r"((r)[12]), "=r"((r)[13]), "=r"((r)[14]), "=r"((r)[15]), \
          "=r"((r)[16]), "=r"((r)[17]), "=r"((r)[18]), "=r"((r)[19]), \
          "=r"((r)[20]), "=r"((r)[21]), "=r"((r)[22]), "=r"((r)[23]), \
          "=r"((r)[24]), "=r"((r)[25]), "=r"((r)[26]), "=r"((r)[27]), \
          "=r"((r)[28]), "=r"((r)[29]), "=r"((r)[30]), "=r"((r)[31]) \
        : "r"(ta))

static constexpr uint64_t SMEM_DESC_BASE_SW128 =
    (uint64_t(2) << 61) | (uint64_t(1) << 46) | (uint64_t(64) << 32) | (uint64_t(1) << 16);
#define MAKE_SMEM_DESC(ba) (SMEM_DESC_BASE_SW128 | ((uint64_t)((ba) >> 4) & 0x3FFF))

__device__ __forceinline__ void mma_f16_ss_cg1(uint32_t d, uint64_t ad, uint64_t bd,
                                               uint32_t idesc, uint32_t en) {
    asm volatile(
        "{\n\t.reg .pred p;\n\tsetp.ne.u32 p, %5, 0;\n\t"
        "tcgen05.mma.cta_group::1.kind::f16 [%0], %1, %2, %3, {%4, %4, %4, %4}, p;\n\t}"
        :: "r"(d), "l"(ad), "l"(bd), "r"(idesc), "r"(0u), "r"(en) : "memory");
}
#endif  // HAS_TCGEN05

// ---------------- split-bf16 helpers ----------------------------------------
__device__ __forceinline__ void split2(float x, unsigned short& h, unsigned short& l) {
    __nv_bfloat16 hb = __float2bfloat16(x);
    __nv_bfloat16 lb = __float2bfloat16(x - __bfloat162float(hb));
    h = __bfloat16_as_ushort(hb);
    l = __bfloat16_as_ushort(lb);
}

// ---- conv: [M,2048] fp32 -> [M,4096] bf16  (hi block | lo block) -----------
template<int SRC>
__global__ __launch_bounds__(256) void conv_split(const float* __restrict__ xin)
{
    const float* src = (SRC == 0) ? xin : g_ao;
    __nv_bfloat16* dst = (SRC == 0) ? g_xs : g_aos;
    const int NG = MROWS * GK / 8;
    for (int g = blockIdx.x * blockDim.x + threadIdx.x; g < NG; g += gridDim.x * blockDim.x) {
        const int m  = g >> 8;
        const int kb = (g & 255) << 3;
        const float4 v0 = *(const float4*)&src[(size_t)m * GK + kb];
        const float4 v1 = *(const float4*)&src[(size_t)m * GK + kb + 4];
        unsigned short h[8], l[8];
        split2(v0.x, h[0], l[0]); split2(v0.y, h[1], l[1]);
        split2(v0.z, h[2], l[2]); split2(v0.w, h[3], l[3]);
        split2(v1.x, h[4], l[4]); split2(v1.y, h[5], l[5]);
        split2(v1.z, h[6], l[6]); split2(v1.w, h[7], l[7]);
        uint4 ho, lo;
        ho.x = (uint32_t)h[0] | ((uint32_t)h[1] << 16);
        ho.y = (uint32_t)h[2] | ((uint32_t)h[3] << 16);
        ho.z = (uint32_t)h[4] | ((uint32_t)h[5] << 16);
        ho.w = (uint32_t)h[6] | ((uint32_t)h[7] << 16);
        lo.x = (uint32_t)l[0] | ((uint32_t)l[1] << 16);
        lo.y = (uint32_t)l[2] | ((uint32_t)l[3] << 16);
        lo.z = (uint32_t)l[4] | ((uint32_t)l[5] << 16);
        lo.w = (uint32_t)l[6] | ((uint32_t)l[7] << 16);
        *(uint4*)&dst[(size_t)m * KA + kb]        = ho;
        *(uint4*)&dst[(size_t)m * KA + 2048 + kb] = lo;
    }
}

// ---- conv: W [K,N] fp32 -> Wt [N,4096] bf16 (all 4 weights, z-indexed) -----
__global__ __launch_bounds__(256) void conv_wT_all(
    const float* __restrict__ wq, const float* __restrict__ wk,
    const float* __restrict__ wv, const float* __restrict__ wo)
{
    __shared__ float smt[32][33];
    const int idx = blockIdx.z;
    const float* W = (idx == 0) ? wq : (idx == 1) ? wk : (idx == 2) ? wv : wo;
    const int k0 = blockIdx.y * 32, n0 = blockIdx.x * 32;
    const int tx = threadIdx.x, ty = threadIdx.y;  // 32x8
#pragma unroll
    for (int r = 0; r < 4; r++)
        smt[ty + 8 * r][tx] = W[(size_t)(k0 + ty + 8 * r) * GN + n0 + tx];
    __syncthreads();
#pragma unroll
    for (int r = 0; r < 4; r++) {
        const int n = n0 + ty + 8 * r;
        const int k = k0 + tx;
        unsigned short h, l;
        split2(smt[tx][ty + 8 * r], h, l);
        *(unsigned short*)&g_ws[idx][(size_t)n * KA + k]        = h;
        *(unsigned short*)&g_ws[idx][(size_t)n * KA + 2048 + k] = l;
    }
}

// ---------------- GEMM: D[128,256] per CTA, 3-term split, 3-stage -----------
// mode = mode_base + blockIdx.z:
//   0: Q -> RoPE -> g_q   1: K -> RoPE -> g_k   2: V -> g_v   3: O-proj -> out
#define TBK     64
#define TN      256
#define SM_TMEM 0
#define SM_MB(s) (8 + 8 * (s))
#define STG_SZ   49152
#define SM_A(s)  (1024 + (s) * STG_SZ)
#define SM_B(s)  (SM_A(s) + 16384)
#define TG_SMEM  (1024 + 3 * STG_SZ)

__global__ __launch_bounds__(256) void tgemm_all(
    int mode_base,
    const float* __restrict__ x_fp, const float* __restrict__ wq,
    const float* __restrict__ wk,   const float* __restrict__ wv,
    const float* __restrict__ wo,
    const float* __restrict__ bq,   const float* __restrict__ bk,
    const float* __restrict__ bv,   const float* __restrict__ bo,
    float* __restrict__ outp,
    const float* __restrict__ cosT, const float* __restrict__ sinT)
{
    const int mode = mode_base + blockIdx.z;
    const float* bias = (mode == 0) ? bq : (mode == 1) ? bk : (mode == 2) ? bv : bo;

#if HAS_TCGEN05
    const uint32_t sb = smem_u32(dyn_smem);
    const int tid = threadIdx.x;
    const int wid = tid >> 5, lid = tid & 31;
    const int m0 = blockIdx.y * 128, n0 = blockIdx.x * TN;

    const __nv_bfloat16* Ain = (mode == 3) ? g_aos : g_xs;
    const __nv_bfloat16* Bin = &g_ws[mode][0];

    if (wid == 0) TCGEN05_ALLOC(sb + SM_TMEM, 256);
    if (tid == 0) {
        MBARRIER_INIT(SM_MB(0) + sb, 1);
        MBARRIER_INIT(SM_MB(1) + sb, 1);
        MBARRIER_INIT(SM_MB(2) + sb, 1);
    }
    __syncthreads();
    uint32_t tmem;
    asm volatile("ld.shared.b32 %0, [%1];" : "=r"(tmem) : "r"(sb + SM_TMEM));

    const int arow = tid >> 1, ac16 = (tid & 1) << 2;
    const int bc16 = tid & 7;
    uint4 va[4], vb[8];

    auto ldg = [&](int kt) {
        const int acol = (kt < 32) ? kt * TBK : (kt < 64) ? 2048 + (kt - 32) * TBK
                                              : (kt - 64) * TBK;
        const int bcol = (kt < 32) ? kt * TBK : (kt < 64) ? (kt - 32) * TBK
                                              : 2048 + (kt - 64) * TBK;
#pragma unroll
        for (int i = 0; i < 4; i++)
            va[i] = *(const uint4*)&Ain[(size_t)(m0 + arow) * KA + acol + (ac16 + i) * 8];
#pragma unroll
        for (int i = 0; i < 8; i++)
            vb[i] = *(const uint4*)&Bin[(size_t)(n0 + (tid >> 3) + i * 32) * KA + bcol + bc16 * 8];
    };
    auto sts = [&](int st) {
#pragma unroll
        for (int i = 0; i < 4; i++) {
            const uint32_t so = SW128((uint32_t)(arow * 128 + (ac16 + i) * 16));
            *(uint4*)(dyn_smem + SM_A(st) + so) = va[i];
        }
#pragma unroll
        for (int i = 0; i < 8; i++) {
            const int r = (tid >> 3) + i * 32;
            const uint32_t so = SW128((uint32_t)(r * 128 + bc16 * 16));
            *(uint4*)(dyn_smem + SM_B(st) + so) = vb[i];
        }
    };

    ldg(0); sts(0);
    ldg(1); sts(1);
    FENCE_PROXY_ASYNC();
    __syncthreads();

    const uint32_t idesc = (1u << 4) | (1u << 7) | (1u << 10) | ((TN / 8) << 17) | (8u << 24);
    int ph[3] = {0, 0, 0};

    for (int kt = 0; kt < NT3; kt++) {
        const int cur = kt % 3;
        if (kt + 2 < NT3) ldg(kt + 2);
        if (wid == 0 && elect1()) {
            const uint64_t ad = MAKE_SMEM_DESC(sb + SM_A(cur));
            const uint64_t bd = MAKE_SMEM_DESC(sb + SM_B(cur));
#pragma unroll
            for (int s = 0; s < 4; s++)
                mma_f16_ss_cg1(tmem, ad + s * 2, bd + s * 2, idesc,
                               (kt > 0 || s > 0) ? 1u : 0u);
            TCGEN05_COMMIT(sb + SM_MB(cur));
        }
        if (kt + 2 < NT3) {
            const int nx = (kt + 2) % 3;
            if (kt + 2 >= 3) { mbar_wait(sb + SM_MB(nx), ph[nx]); ph[nx] ^= 1; }
            sts(nx);
            FENCE_PROXY_ASYNC();
        }
        __syncthreads();
    }

    mbar_wait(sb + SM_MB(2), ph[2]);
    TCGEN05_FENCE_AFTER();

    if (wid < 4) {
        const int m = m0 + wid * 32 + lid;
        const int bb = m >> 11, s = m & 2047;
#pragma unroll
        for (int nb = 0; nb < 8; nb++) {
            uint32_t r[32];
            TCGEN05_LD_X32(r, tmem + nb * 32);
            TCGEN05_WAIT_LD();
            const int nbase = n0 + nb * 32;
            const int hh = nbase >> 7;
            const int d0 = nbase & 127;
            float w[32];
            if (mode <= 1) {
#pragma unroll
                for (int c = 0; c < 32; c += 2) {
                    const int n = nbase + c;
                    const float v0 = __uint_as_float(r[c])     + bias[n];
                    const float v1 = __uint_as_float(r[c + 1]) + bias[n + 1];
                    const int i0 = (n & 127) >> 1;
                    const float cv = cosT[s * (HEAD_DIM / 2) + i0];
                    const float sv = sinT[s * (HEAD_DIM / 2) + i0];
                    w[c]     = v0 * cv - v1 * sv;
                    w[c + 1] = v0 * sv + v1 * cv;
                }
            } else {
#pragma unroll
                for (int c = 0; c < 32; c++)
                    w[c] = __uint_as_float(r[c]) + bias[nbase + c];
            }
            if (mode == 3) {
#pragma unroll
                for (int c = 0; c < 32; c += 4)
                    *(float4*)&outp[(size_t)m * GN + nbase + c] =
                        make_float4(w[c], w[c + 1], w[c + 2], w[c + 3]);
            } else {
                float* dst = (mode == 0) ? g_q : (mode == 1) ? g_k : g_v;
                const size_t off =
                    ((size_t)(bb * NUM_HEADS + hh) * SEQ + s) * HEAD_DIM + d0;
#pragma unroll
                for (int c = 0; c < 32; c += 4)
                    *(float4*)&dst[off + c] =
                        make_float4(w[c], w[c + 1], w[c + 2], w[c + 3]);
            }
        }
    }
    __syncthreads();
    if (wid == 0) { TCGEN05_RELINQ(); TCGEN05_DEALLOC(tmem, 256); }

#else
    // ============ fallback: proven fp32 scalar GEMM (two 128-wide halves) ============
    float* As = (float*)dyn_smem;
    float* Bs = (float*)dyn_smem + 2 * 16 * 132;
#define AS_(b,k,r) As[((b) * 16 + (k)) * 132 + (r)]
#define BS_(b,k,c) Bs[((b) * 16 + (k)) * 128 + (c)]

    const int tid = threadIdx.x;
    const int m0 = blockIdx.y * 128;
    const float* Ap = (mode == 3) ? g_ao : x_fp;
    const float* W  = (mode == 0) ? wq : (mode == 1) ? wk : (mode == 2) ? wv : wo;

    const int r0 = (tid >> 4) << 3;
    const int c0 = (tid & 15) << 3;

    int a_row[2], a_k[2], b_row[2], b_col[2];
#pragma unroll
    for (int j = 0; j < 2; j++) {
        int lin = tid + j * 256;
        a_row[j] = lin >> 2;  a_k[j] = (lin & 3) << 2;
        b_row[j] = lin >> 5;  b_col[j] = (lin & 31) << 2;
    }

    for (int nh = 0; nh < 2; nh++) {
        const int n0 = blockIdx.x * TN + nh * 128;
        __syncthreads();

        float acc[8][8];
#pragma unroll
        for (int i = 0; i < 8; i++)
#pragma unroll
            for (int j = 0; j < 8; j++) acc[i][j] = 0.f;

        float4 pa[2], pb[2];
#pragma unroll
        for (int j = 0; j < 2; j++) {
            pa[j] = *(const float4*)&Ap[(size_t)(m0 + a_row[j]) * GK + a_k[j]];
            pb[j] = *(const float4*)&W[(size_t)b_row[j] * GN + n0 + b_col[j]];
        }
#pragma unroll
        for (int j = 0; j < 2; j++) {
            AS_(0, a_k[j] + 0, a_row[j]) = pa[j].x;
            AS_(0, a_k[j] + 1, a_row[j]) = pa[j].y;
            AS_(0, a_k[j] + 2, a_row[j]) = pa[j].z;
            AS_(0, a_k[j] + 3, a_row[j]) = pa[j].w;
            *(float4*)&BS_(0, b_row[j], b_col[j]) = pb[j];
        }
        __syncthreads();

        const int NT = GK / 16;
        for (int kt = 0; kt < NT; kt++) {
            const int cur = kt & 1;
            if (kt + 1 < NT) {
#pragma unroll
                for (int j = 0; j < 2; j++) {
                    pa[j] = *(const float4*)&Ap[(size_t)(m0 + a_row[j]) * GK + (kt + 1) * 16 + a_k[j]];
                    pb[j] = *(const float4*)&W[(size_t)((kt + 1) * 16 + b_row[j]) * GN + n0 + b_col[j]];
                }
            }
#pragma unroll
            for (int kk = 0; kk < 16; kk++) {
                float a[8], b[8];
                *(float4*)&a[0] = *(const float4*)&AS_(cur, kk, r0);
                *(float4*)&a[4] = *(const float4*)&AS_(cur, kk, r0 + 4);
                *(float4*)&b[0] = *(const float4*)&BS_(cur, kk, c0);
                *(float4*)&b[4] = *(const float4*)&BS_(cur, kk, c0 + 4);
#pragma unroll
                for (int i = 0; i < 8; i++)
#pragma unroll
                    for (int j = 0; j < 8; j++)
                        acc[i][j] += a[i] * b[j];
            }
            if (kt + 1 < NT) {
                const int nxt = cur ^ 1;
#pragma unroll
                for (int j = 0; j < 2; j++) {
                    AS_(nxt, a_k[j] + 0, a_row[j]) = pa[j].x;
                    AS_(nxt, a_k[j] + 1, a_row[j]) = pa[j].y;
                    AS_(nxt, a_k[j] + 2, a_row[j]) = pa[j].z;
                    AS_(nxt, a_k[j] + 3, a_row[j]) = pa[j].w;
                    *(float4*)&BS_(nxt, b_row[j], b_col[j]) = pb[j];
                }
            }
            __syncthreads();
        }

        float bv8[8];
        *(float4*)&bv8[0] = *(const float4*)&bias[n0 + c0];
        *(float4*)&bv8[4] = *(const float4*)&bias[n0 + c0 + 4];

#pragma unroll
        for (int i = 0; i < 8; i++) {
            const int m = m0 + r0 + i;
            float v[8];
#pragma unroll
            for (int j = 0; j < 8; j++) v[j] = acc[i][j] + bv8[j];

            if (mode == 3) {
                *(float4*)&outp[(size_t)m * GN + n0 + c0]     = make_float4(v[0], v[1], v[2], v[3]);
                *(float4*)&outp[(size_t)m * GN + n0 + c0 + 4] = make_float4(v[4], v[5], v[6], v[7]);
            } else {
                const int bb = m >> 11;
                const int s  = m & 2047;
                const int hh = (n0 + c0) >> 7;
                const int d0 = (n0 + c0) & 127;
                float w[8];
                if (mode <= 1) {
                    const int i0 = d0 >> 1;
#pragma unroll
                    for (int p = 0; p < 4; p++) {
                        float cv = cosT[s * (HEAD_DIM / 2) + i0 + p];
                        float sv = sinT[s * (HEAD_DIM / 2) + i0 + p];
                        w[2 * p]     = v[2 * p] * cv - v[2 * p + 1] * sv;
                        w[2 * p + 1] = v[2 * p] * sv + v[2 * p + 1] * cv;
                    }
                } else {
#pragma unroll
                    for (int j = 0; j < 8; j++) w[j] = v[j];
                }
                float* dst = (mode == 0) ? g_q : (mode == 1) ? g_k : g_v;
                size_t o = ((size_t)(bb * NUM_HEADS + hh) * SEQ + s) * HEAD_DIM + d0;
                *(float4*)&dst[o]     = make_float4(w[0], w[1], w[2], w[3]);
                *(float4*)&dst[o + 4] = make_float4(w[4], w[5], w[6], w[7]);
            }
        }
    }
#undef AS_
#undef BS_
#endif  // HAS_TCGEN05
}

// ---------------- flash attention (causal), fp32 — proven R4 version -------
#define ATTN_SMEM_BYTES  (29376 * 4)

__global__ __launch_bounds__(256, 1) void attn_kernel()
{
    float* sm = (float*)dyn_smem;
    float* Qs   = sm;
    float* Ks   = sm + 8192;
    float* Vs   = sm + 16640;
    float* Ss   = sm + 24832;
    float* rowm = sm + 29184;
    float* rowl = sm + 29248;
    float* rowa = sm + 29312;

    const int tid = threadIdx.x;
    const int qt = blockIdx.x, h = blockIdx.y, b = blockIdx.z;
    const int q0 = qt * 64;
    const size_t base = ((size_t)(b * NUM_HEADS + h)) * SEQ * HEAD_DIM;
    const float scale = 0.088388347648318447f;  // 1/sqrt(128)

    for (int idx = tid; idx < 2048; idx += 256) {
        int r = idx >> 5, c4 = (idx & 31) << 2;
        float4 v = *(const float4*)&g_q[base + (size_t)(q0 + r) * HEAD_DIM + c4];
        v.x *= scale; v.y *= scale; v.z *= scale; v.w *= scale;
        *(float4*)&Qs[r * 128 + c4] = v;
    }
    if (tid < 64) { rowm[tid] = -1e30f; rowl[tid] = 0.f; }

    const int org = tid >> 5;
    const int ocg = tid & 31;
    const int srg = tid >> 4;
    const int scg = tid & 15;

    float oacc[8][4];
#pragma unroll
    for (int i = 0; i < 8; i++)
#pragma unroll
        for (int u = 0; u < 4; u++) oacc[i][u] = 0.f;

    for (int t = 0; t <= qt; t++) {
        const int kv0 = t * 64;
        __syncthreads();
        for (int idx = tid; idx < 2048; idx += 256) {
            int r = idx >> 5, c4 = (idx & 31) << 2;
            *(float4*)&Ks[r * 132 + c4] =
                *(const float4*)&g_k[base + (size_t)(kv0 + r) * HEAD_DIM + c4];
            *(float4*)&Vs[r * 128 + c4] =
                *(const float4*)&g_v[base + (size_t)(kv0 + r) * HEAD_DIM + c4];
        }
        __syncthreads();

        float sacc[4][4];
#pragma unroll
        for (int i = 0; i < 4; i++)
#pragma unroll
            for (int j = 0; j < 4; j++) sacc[i][j] = 0.f;

#pragma unroll 8
        for (int c = 0; c < 128; c += 4) {
            float4 q4[4], k4[4];
#pragma unroll
            for (int i = 0; i < 4; i++)
                q4[i] = *(const float4*)&Qs[(srg * 4 + i) * 128 + c];
#pragma unroll
            for (int j = 0; j < 4; j++)
                k4[j] = *(const float4*)&Ks[(scg + 16 * j) * 132 + c];
#pragma unroll
            for (int i = 0; i < 4; i++)
#pragma unroll
                for (int j = 0; j < 4; j++)
                    sacc[i][j] += q4[i].x * k4[j].x + q4[i].y * k4[j].y +
                                  q4[i].z * k4[j].z + q4[i].w * k4[j].w;
        }
#pragma unroll
        for (int i = 0; i < 4; i++) {
            const int qg = q0 + srg * 4 + i;
#pragma unroll
            for (int j = 0; j < 4; j++) {
                const int kg = kv0 + scg + 16 * j;
                Ss[(srg * 4 + i) * 68 + scg + 16 * j] =
                    (kg <= qg) ? sacc[i][j] : -1e30f;
            }
        }
        __syncthreads();

        {
            const int row = tid >> 2, seg = tid & 3;
            float* srow = &Ss[row * 68 + seg * 16];
            const float mold = rowm[row];
            float mx = -1e30f;
#pragma unroll
            for (int j = 0; j < 16; j++) mx = fmaxf(mx, srow[j]);
            mx = fmaxf(mx, __shfl_xor_sync(0xffffffffu, mx, 1));
            mx = fmaxf(mx, __shfl_xor_sync(0xffffffffu, mx, 2));
            mx = fmaxf(mx, mold);
            float ls = 0.f;
#pragma unroll
            for (int j = 0; j < 16; j++) {
                float p = __expf(srow[j] - mx);
                srow[j] = p;
                ls += p;
            }
            ls += __shfl_xor_sync(0xffffffffu, ls, 1);
            ls += __shfl_xor_sync(0xffffffffu, ls, 2);
            if (seg == 0) {
                float alpha = __expf(mold - mx);
                rowa[row] = alpha;
                rowl[row] = rowl[row] * alpha + ls;
                rowm[row] = mx;
            }
        }
        __syncthreads();

#pragma unroll
        for (int i = 0; i < 8; i++) {
            float a = rowa[org * 8 + i];
#pragma unroll
            for (int u = 0; u < 4; u++) oacc[i][u] *= a;
        }
#pragma unroll 4
        for (int j = 0; j < 64; j += 4) {
            float4 v0 = *(const float4*)&Vs[(j + 0) * 128 + ocg * 4];
            float4 v1 = *(const float4*)&Vs[(j + 1) * 128 + ocg * 4];
            float4 v2 = *(const float4*)&Vs[(j + 2) * 128 + ocg * 4];
            float4 v3 = *(const float4*)&Vs[(j + 3) * 128 + ocg * 4];
#pragma unroll
            for (int i = 0; i < 8; i++) {
                float4 p = *(const float4*)&Ss[(org * 8 + i) * 68 + j];
                oacc[i][0] += p.x * v0.x + p.y * v1.x + p.z * v2.x + p.w * v3.x;
                oacc[i][1] += p.x * v0.y + p.y * v1.y + p.z * v2.y + p.w * v3.y;
                oacc[i][2] += p.x * v0.z + p.y * v1.z + p.z * v2.z + p.w * v3.z;
                oacc[i][3] += p.x * v0.w + p.y * v1.w + p.z * v2.w + p.w * v3.w;
            }
        }
    }

#pragma unroll
    for (int i = 0; i < 8; i++) {
        const int row = org * 8 + i;
        const float il = 1.0f / rowl[row];
        size_t o = ((size_t)(b * SEQ + q0 + row)) * HIDDEN + h * HEAD_DIM + ocg * 4;
        *(float4*)&g_ao[o] = make_float4(oacc[i][0] * il, oacc[i][1] * il,
                                         oacc[i][2] * il, oacc[i][3] * il);
    }
}

// ---------------- launch ---------------------------------------------------
extern "C" void kernel_launch(void* const* d_in, const int* in_sizes, int n_in,
                              void* d_out, int out_size)
{
    const float* x    = (const float*)d_in[0];
    const float* wq   = (const float*)d_in[1];
    const float* bq   = (const float*)d_in[2];
    const float* wk   = (const float*)d_in[3];
    const float* bk_  = (const float*)d_in[4];
    const float* wv   = (const float*)d_in[5];
    const float* bv   = (const float*)d_in[6];
    const float* wo   = (const float*)d_in[7];
    const float* bo   = (const float*)d_in[8];
    const float* cosT = (const float*)d_in[9];
    const float* sinT = (const float*)d_in[10];
    float* out = (float*)d_out;

    cudaFuncSetAttribute(tgemm_all, cudaFuncAttributeMaxDynamicSharedMemorySize, TG_SMEM);
    cudaFuncSetAttribute(attn_kernel, cudaFuncAttributeMaxDynamicSharedMemorySize, ATTN_SMEM_BYTES);

    // split conversions (merged W transpose: one launch, z = weight index)
    conv_split<0><<<4096, 256>>>(x);
    conv_wT_all<<<dim3(GN / 32, GK / 32, 4), dim3(32, 8)>>>(wq, wk, wv, wo);

    // Q, K, V projections in ONE launch (z = mode)
    tgemm_all<<<dim3(GN / TN, MROWS / 128, 3), 256, TG_SMEM>>>(
        0, x, wq, wk, wv, wo, bq, bk_, bv, bo, out, cosT, sinT);

    attn_kernel<<<dim3(SEQ / 64, NUM_HEADS, BATCH), 256, ATTN_SMEM_BYTES>>>();

    conv_split<1><<<4096, 256>>>(nullptr);
    tgemm_all<<<dim3(GN / TN, MROWS / 128, 1), 256, TG_SMEM>>>(
        3, x, wq, wk, wv, wo, bq, bk_, bv, bo, out, cosT, sinT);
}